// round 6
// baseline (speedup 1.0000x reference)
#include <cuda_runtime.h>
#include <cuda_fp16.h>
#include <stdint.h>

#define NN 8192
#define NITER 50
#define CSTAR 0.00390625f   /* 2^-8 */
/* decoded K = K_true * 2^-14; r scaled by 2^-22, c unscaled (see k_final) */

static __device__ __align__(256) uint32_t g_K8[(size_t)NN * NN / 4];
static __device__ __align__(16) float g_r[(NITER + 1) * NN];  // atomic-accum slices
static __device__ __align__(16) float g_c[(NITER + 1) * NN];  // atomic-accum slices
static __device__ float g_trow[NN];
static __device__ float g_tcol[NN];
static __device__ float g_S1[1];

static __device__ __forceinline__ __half2 u2h(uint32_t x) {
    return *reinterpret_cast<__half2*>(&x);
}
// two e4m3 bytes (sign=0) -> half2 of value*2^-8, exact (incl. subnormals)
static __device__ __forceinline__ __half2 dE(uint32_t q) {  // bytes 0,2
    return u2h((q << 7) & 0x7F807F80u);
}
static __device__ __forceinline__ __half2 dO(uint32_t q) {  // bytes 1,3
    return u2h((q >> 1) & 0x7F807F80u);
}
static __device__ __forceinline__ float ex2f(float x) {
    float r; asm("ex2.approx.f32 %0, %1;" : "=f"(r) : "f"(x)); return r;
}
static __device__ __forceinline__ uint32_t packh2(float a, float b) {
    const uint32_t ua = __half_as_ushort(__float2half_rn(a));
    const uint32_t ub = __half_as_ushort(__float2half_rn(b));
    return ua | (ub << 16);
}

// ---------------------------------------------------------------------------
__global__ void k_init() {
    const int n = (NITER + 1) * NN;   // 417792 == 1632*256
    for (int i = blockIdx.x * blockDim.x + threadIdx.x; i < n;
         i += gridDim.x * blockDim.x) {
        g_r[i] = 0.0f;
        g_c[i] = (i < NN) ? 1.0f : 0.0f;
        if (i < NN) { g_trow[i] = 0.0f; g_tcol[i] = 0.0f; }
        if (i == 0) g_S1[0] = 0.0f;
    }
}

// ---------------------------------------------------------------------------
// fused build + target reductions. One pass over M and target:
//   K8 = e4m3(exp2(M*10/ln2 - 6)), S1 = sum(t*M), trow/tcol marginals of t.
// grid (8, 64), 256 thr: tile = 128 rows x 1024 cols.
// ---------------------------------------------------------------------------
__global__ void __launch_bounds__(256) k_bt(const float* __restrict__ M,
                                            const float* __restrict__ tgt) {
    const int r0 = blockIdx.y << 7;
    const int c0 = blockIdx.x << 10;
    const int t  = threadIdx.x;
    const int lane = t & 31;
    const float4* __restrict__ pm =
        (const float4*)(M + (size_t)r0 * NN + c0) + t;
    const float4* __restrict__ pt =
        (const float4*)(tgt + (size_t)r0 * NN + c0) + t;
    uint32_t* __restrict__ pk = g_K8 + (size_t)r0 * (NN / 4) + (c0 >> 2) + t;

    float cx = 0.f, cy = 0.f, cz = 0.f, cw = 0.f, dot = 0.f;
    for (int r = 0; r < 128; r++) {
        const float4 m4 = pm[r * (NN / 4)];
        const float4 t4 = pt[r * (NN / 4)];
        const float e0 = ex2f(fmaf(14.42695041f, m4.x, -6.0f));
        const float e1 = ex2f(fmaf(14.42695041f, m4.y, -6.0f));
        const float e2 = ex2f(fmaf(14.42695041f, m4.z, -6.0f));
        const float e3 = ex2f(fmaf(14.42695041f, m4.w, -6.0f));
        unsigned short lo, hi;
        asm("cvt.rn.satfinite.e4m3x2.f32 %0, %1, %2;" : "=h"(lo) : "f"(e1), "f"(e0));
        asm("cvt.rn.satfinite.e4m3x2.f32 %0, %1, %2;" : "=h"(hi) : "f"(e3), "f"(e2));
        pk[r * (NN / 4)] = (uint32_t)lo | ((uint32_t)hi << 16);

        cx += t4.x; cy += t4.y; cz += t4.z; cw += t4.w;
        dot = fmaf(t4.x, m4.x, dot);
        dot = fmaf(t4.y, m4.y, dot);
        dot = fmaf(t4.z, m4.z, dot);
        dot = fmaf(t4.w, m4.w, dot);
        float s4 = (t4.x + t4.y) + (t4.z + t4.w);
#pragma unroll
        for (int o = 16; o; o >>= 1)
            s4 += __shfl_xor_sync(0xFFFFFFFFu, s4, o);
        if (lane == 0) atomicAdd(&g_trow[r0 + r], s4);
    }
    float* tc = g_tcol + c0 + (t << 2);
    atomicAdd(tc + 0, cx);
    atomicAdd(tc + 1, cy);
    atomicAdd(tc + 2, cz);
    atomicAdd(tc + 3, cw);

    __shared__ float sred[256];
    sred[t] = dot;
    __syncthreads();
    for (int s = 128; s > 0; s >>= 1) {
        if (t < s) sred[t] += sred[t + s];
        __syncthreads();
    }
    if (t == 0) atomicAdd(&g_S1[0], sred[0]);
}

// ---------------------------------------------------------------------------
// passA: r[i] += sum_{j in col-half} Kd[i,j] * (CSTAR / c[j])
// grid (2, 512): blockIdx.x = column half (4096 cols), blockIdx.y = 16 rows.
// Warp = 2 rows x 4096 cols. Weights pair-shuffled half2 in smem (8 KB).
// 2-way fp32 atomic combine into zeroed r slice (commutative -> deterministic).
// ---------------------------------------------------------------------------
__global__ void __launch_bounds__(256, 3) k_passA(const float* __restrict__ vin,
                                                  float* __restrict__ vout) {
    __shared__ uint32_t sw[2048];   // 4096 cols -> 2048 half2 words
    const int t  = threadIdx.x;
    const int cb = blockIdx.x << 12;         // 0 or 4096
#pragma unroll
    for (int k = 0; k < 4; k++) {
        const int g = t + (k << 8);          // 0..1023, 4 cols each
        const float4 c4 = *(const float4*)(vin + cb + (g << 2));
        sw[2 * g]     = packh2(__fdividef(CSTAR, c4.x), __fdividef(CSTAR, c4.z));
        sw[2 * g + 1] = packh2(__fdividef(CSTAR, c4.y), __fdividef(CSTAR, c4.w));
    }
    __syncthreads();

    const int w = t >> 5, lane = t & 31;
    const int rowa = (blockIdx.y << 4) + (w << 1);
    const uint4* __restrict__ pa =
        ((const uint4*)g_K8) + (size_t)rowa * (NN / 16) + (cb >> 4) + lane;
    const uint4* __restrict__ pb = pa + (NN / 16);
    const uint4* __restrict__ swv = ((const uint4*)sw) + (lane << 1);

    const __half2 z = __floats2half2_rn(0.f, 0.f);
    __half2 aE0 = z, aO0 = z, aE1 = z, aO1 = z;
    __half2 bE0 = z, bO0 = z, bE1 = z, bO1 = z;

#pragma unroll
    for (int s = 0; s < 8; s += 2) {
        const uint4 qa0 = pa[s * 32];
        const uint4 qa1 = pa[(s + 1) * 32];
        const uint4 qb0 = pb[s * 32];
        const uint4 qb1 = pb[(s + 1) * 32];
        const uint4 w0 = swv[(s << 6)];
        const uint4 w1 = swv[(s << 6) + 1];
        const uint4 w2 = swv[((s + 1) << 6)];
        const uint4 w3 = swv[((s + 1) << 6) + 1];

        aE0 = __hfma2(dE(qa0.x), u2h(w0.x), aE0);
        aO0 = __hfma2(dO(qa0.x), u2h(w0.y), aO0);
        aE1 = __hfma2(dE(qa0.y), u2h(w0.z), aE1);
        aO1 = __hfma2(dO(qa0.y), u2h(w0.w), aO1);
        aE0 = __hfma2(dE(qa0.z), u2h(w1.x), aE0);
        aO0 = __hfma2(dO(qa0.z), u2h(w1.y), aO0);
        aE1 = __hfma2(dE(qa0.w), u2h(w1.z), aE1);
        aO1 = __hfma2(dO(qa0.w), u2h(w1.w), aO1);
        aE0 = __hfma2(dE(qa1.x), u2h(w2.x), aE0);
        aO0 = __hfma2(dO(qa1.x), u2h(w2.y), aO0);
        aE1 = __hfma2(dE(qa1.y), u2h(w2.z), aE1);
        aO1 = __hfma2(dO(qa1.y), u2h(w2.w), aO1);
        aE0 = __hfma2(dE(qa1.z), u2h(w3.x), aE0);
        aO0 = __hfma2(dO(qa1.z), u2h(w3.y), aO0);
        aE1 = __hfma2(dE(qa1.w), u2h(w3.z), aE1);
        aO1 = __hfma2(dO(qa1.w), u2h(w3.w), aO1);

        bE0 = __hfma2(dE(qb0.x), u2h(w0.x), bE0);
        bO0 = __hfma2(dO(qb0.x), u2h(w0.y), bO0);
        bE1 = __hfma2(dE(qb0.y), u2h(w0.z), bE1);
        bO1 = __hfma2(dO(qb0.y), u2h(w0.w), bO1);
        bE0 = __hfma2(dE(qb0.z), u2h(w1.x), bE0);
        bO0 = __hfma2(dO(qb0.z), u2h(w1.y), bO0);
        bE1 = __hfma2(dE(qb0.w), u2h(w1.z), bE1);
        bO1 = __hfma2(dO(qb0.w), u2h(w1.w), bO1);
        bE0 = __hfma2(dE(qb1.x), u2h(w2.x), bE0);
        bO0 = __hfma2(dO(qb1.x), u2h(w2.y), bO0);
        bE1 = __hfma2(dE(qb1.y), u2h(w2.z), bE1);
        bO1 = __hfma2(dO(qb1.y), u2h(w2.w), bO1);
        bE0 = __hfma2(dE(qb1.z), u2h(w3.x), bE0);
        bO0 = __hfma2(dO(qb1.z), u2h(w3.y), bO0);
        bE1 = __hfma2(dE(qb1.w), u2h(w3.z), bE1);
        bO1 = __hfma2(dO(qb1.w), u2h(w3.w), bO1);
    }

    __half2 sa = __hadd2(__hadd2(aE0, aO0), __hadd2(aE1, aO1));
    __half2 sb = __hadd2(__hadd2(bE0, bO0), __hadd2(bE1, bO1));
    float va = __low2float(sa) + __high2float(sa);
    float vb = __low2float(sb) + __high2float(sb);
#pragma unroll
    for (int o = 16; o; o >>= 1) {
        va += __shfl_xor_sync(0xFFFFFFFFu, va, o);
        vb += __shfl_xor_sync(0xFFFFFFFFu, vb, o);
    }
    if (lane == 0) {
        atomicAdd(&vout[rowa], va);
        atomicAdd(&vout[rowa + 1], vb);
    }
}

// ---------------------------------------------------------------------------
// passB: c[j] += sum_{i in row-group} Kd[i,j] * (CSTAR / r[i])
// grid (4, 256): block = 32 rows x 2048 cols, thread = 8 cols (uint2/row),
// 8-deep load batches; one fp16->fp32 flush; 8 atomics into zeroed c slice.
// ---------------------------------------------------------------------------
__global__ void __launch_bounds__(256, 4) k_passB(const float* __restrict__ vin,
                                                  float* __restrict__ vout) {
    __shared__ uint32_t swr[32];
    const int t  = threadIdx.x;
    const int r0 = blockIdx.y << 5;
    const int c0 = (blockIdx.x << 11) + (t << 3);
    if (t < 32) {
        const float wv = __fdividef(CSTAR, vin[r0 + t]);
        swr[t] = packh2(wv, wv);
    }
    __syncthreads();

    const uint2* __restrict__ base =
        ((const uint2*)g_K8) + (size_t)r0 * (NN / 8) + (c0 >> 3);

    const __half2 z = __floats2half2_rn(0.f, 0.f);
    __half2 hE0 = z, hO0 = z, hE1 = z, hO1 = z;

#pragma unroll
    for (int rb = 0; rb < 32; rb += 8) {
        uint2 q[8];
#pragma unroll
        for (int k = 0; k < 8; k++)
            q[k] = base[(size_t)(rb + k) * (NN / 8)];
#pragma unroll
        for (int k = 0; k < 8; k++) {
            const __half2 wr = u2h(swr[rb + k]);
            hE0 = __hfma2(dE(q[k].x), wr, hE0);
            hO0 = __hfma2(dO(q[k].x), wr, hO0);
            hE1 = __hfma2(dE(q[k].y), wr, hE1);
            hO1 = __hfma2(dO(q[k].y), wr, hO1);
        }
    }

    float* vo = vout + c0;
    atomicAdd(vo + 0, __low2float(hE0));
    atomicAdd(vo + 1, __low2float(hO0));
    atomicAdd(vo + 2, __high2float(hE0));
    atomicAdd(vo + 3, __high2float(hO0));
    atomicAdd(vo + 4, __low2float(hE1));
    atomicAdd(vo + 5, __low2float(hO1));
    atomicAdd(vo + 6, __high2float(hE1));
    atomicAdd(vo + 7, __high2float(hO1));
}

// ---------------------------------------------------------------------------
// loss = -10*S1 + 35*ln2*S3 + <trow, ln r50> + <tcol, ln c50>
// ---------------------------------------------------------------------------
__global__ void __launch_bounds__(1024) k_final(float* __restrict__ out) {
    const int t = threadIdx.x;
    const float* rfin = g_r + (size_t)NITER * NN;
    const float* cfin = g_c + (size_t)NITER * NN;
    float s1 = 0.f, s2 = 0.f, s3 = 0.f;
    for (int i = t; i < NN; i += 1024) {
        const float tr = g_trow[i];
        s1 += tr * logf(rfin[i]);
        s3 += tr;
        s2 += g_tcol[i] * logf(cfin[i]);
    }
    __shared__ float sa[1024], sb[1024], sc[1024];
    sa[t] = s1; sb[t] = s2; sc[t] = s3;
    __syncthreads();
    for (int s = 512; s > 0; s >>= 1) {
        if (t < s) { sa[t] += sa[t + s]; sb[t] += sb[t + s]; sc[t] += sc[t + s]; }
        __syncthreads();
    }
    if (t == 0)
        out[0] = -10.0f * g_S1[0] + 24.260151319598086f * sc[0] + sa[0] + sb[0];
}

// ---------------------------------------------------------------------------
extern "C" void kernel_launch(void* const* d_in, const int* in_sizes, int n_in,
                              void* d_out, int out_size) {
    (void)in_sizes; (void)n_in; (void)out_size;
    const float* M   = (const float*)d_in[0];
    const float* tgt = (const float*)d_in[1];
    float* out = (float*)d_out;

    void *pR, *pC;
    cudaGetSymbolAddress(&pR, g_r);
    cudaGetSymbolAddress(&pC, g_c);
    float* R = (float*)pR;
    float* C = (float*)pC;

    k_init<<<1632, 256>>>();
    k_bt<<<dim3(8, 64), 256>>>(M, tgt);

    for (int k = 1; k <= NITER; k++) {
        k_passA<<<dim3(2, 512), 256>>>(C + (size_t)(k - 1) * NN,
                                       R + (size_t)k * NN);
        k_passB<<<dim3(4, 256), 256>>>(R + (size_t)k * NN,
                                       C + (size_t)k * NN);
    }
    k_final<<<1, 1024>>>(out);
}

// round 7
// speedup vs baseline: 1.3891x; 1.3891x over previous
#include <cuda_runtime.h>
#include <cuda_fp16.h>
#include <stdint.h>

#define NN 8192
#define NITER 50
#define CSTAR 0.00390625f   /* 2^-8 */
/* decoded K = K_true * 2^-14; r scaled by 2^-22, c unscaled (see k_final) */

static __device__ __align__(256) uint32_t g_K8[(size_t)NN * NN / 4];
static __device__ __align__(16) float g_r[(NITER + 1) * NN];
static __device__ __align__(16) float g_c[(NITER + 1) * NN];  // atomic-accum slices
static __device__ float g_trow[NN];
static __device__ float g_tcol[NN];
static __device__ float g_S1[1];

static __device__ __forceinline__ __half2 u2h(uint32_t x) {
    return *reinterpret_cast<__half2*>(&x);
}
// two e4m3 bytes (sign=0) -> half2 of value*2^-8, exact (incl. subnormals)
static __device__ __forceinline__ __half2 dE(uint32_t q) {  // bytes 0,2
    return u2h((q << 7) & 0x7F807F80u);
}
static __device__ __forceinline__ __half2 dO(uint32_t q) {  // bytes 1,3
    return u2h((q >> 1) & 0x7F807F80u);
}
static __device__ __forceinline__ float ex2f(float x) {
    float r; asm("ex2.approx.f32 %0, %1;" : "=f"(r) : "f"(x)); return r;
}
static __device__ __forceinline__ uint32_t packh2(float a, float b) {
    const uint32_t ua = __half_as_ushort(__float2half_rn(a));
    const uint32_t ub = __half_as_ushort(__float2half_rn(b));
    return ua | (ub << 16);
}

// ---------------------------------------------------------------------------
__global__ void k_init() {
    const int n = (NITER + 1) * NN;   // 417792 == 1632*256
    for (int i = blockIdx.x * blockDim.x + threadIdx.x; i < n;
         i += gridDim.x * blockDim.x) {
        g_r[i] = 0.0f;
        g_c[i] = (i < NN) ? 1.0f : 0.0f;
        if (i < NN) { g_trow[i] = 0.0f; g_tcol[i] = 0.0f; }
        if (i == 0) g_S1[0] = 0.0f;
    }
}

// ---------------------------------------------------------------------------
// fused build + target reductions. One pass over M and target:
//   K8 = e4m3(exp2(M*10/ln2 - 6)), S1 = sum(t*M), trow/tcol marginals of t.
// grid (8, 64), 256 thr: tile = 128 rows x 1024 cols.
// ---------------------------------------------------------------------------
__global__ void __launch_bounds__(256) k_bt(const float* __restrict__ M,
                                            const float* __restrict__ tgt) {
    const int r0 = blockIdx.y << 7;
    const int c0 = blockIdx.x << 10;
    const int t  = threadIdx.x;
    const int lane = t & 31;
    const float4* __restrict__ pm =
        (const float4*)(M + (size_t)r0 * NN + c0) + t;
    const float4* __restrict__ pt =
        (const float4*)(tgt + (size_t)r0 * NN + c0) + t;
    uint32_t* __restrict__ pk = g_K8 + (size_t)r0 * (NN / 4) + (c0 >> 2) + t;

    float cx = 0.f, cy = 0.f, cz = 0.f, cw = 0.f, dot = 0.f;
    for (int r = 0; r < 128; r++) {
        const float4 m4 = pm[r * (NN / 4)];
        const float4 t4 = pt[r * (NN / 4)];
        const float e0 = ex2f(fmaf(14.42695041f, m4.x, -6.0f));
        const float e1 = ex2f(fmaf(14.42695041f, m4.y, -6.0f));
        const float e2 = ex2f(fmaf(14.42695041f, m4.z, -6.0f));
        const float e3 = ex2f(fmaf(14.42695041f, m4.w, -6.0f));
        unsigned short lo, hi;
        asm("cvt.rn.satfinite.e4m3x2.f32 %0, %1, %2;" : "=h"(lo) : "f"(e1), "f"(e0));
        asm("cvt.rn.satfinite.e4m3x2.f32 %0, %1, %2;" : "=h"(hi) : "f"(e3), "f"(e2));
        pk[r * (NN / 4)] = (uint32_t)lo | ((uint32_t)hi << 16);

        cx += t4.x; cy += t4.y; cz += t4.z; cw += t4.w;
        dot = fmaf(t4.x, m4.x, dot);
        dot = fmaf(t4.y, m4.y, dot);
        dot = fmaf(t4.z, m4.z, dot);
        dot = fmaf(t4.w, m4.w, dot);
        float s4 = (t4.x + t4.y) + (t4.z + t4.w);
#pragma unroll
        for (int o = 16; o; o >>= 1)
            s4 += __shfl_xor_sync(0xFFFFFFFFu, s4, o);
        if (lane == 0) atomicAdd(&g_trow[r0 + r], s4);
    }
    float* tc = g_tcol + c0 + (t << 2);
    atomicAdd(tc + 0, cx);
    atomicAdd(tc + 1, cy);
    atomicAdd(tc + 2, cz);
    atomicAdd(tc + 3, cw);

    __shared__ float sred[256];
    sred[t] = dot;
    __syncthreads();
    for (int s = 128; s > 0; s >>= 1) {
        if (t < s) sred[t] += sred[t + s];
        __syncthreads();
    }
    if (t == 0) atomicAdd(&g_S1[0], sred[0]);
}

// ---------------------------------------------------------------------------
// passA: r[i] = sum_j Kd[i,j] * (CSTAR / c[j])
// 512 blocks x 256 thr; warp = 2 rows x 8192 cols; weights in smem (16 KB).
// Inner loop: explicit 8-deep uint4 batch (load-all-then-compute) so the
// loads stay live in registers (MLP = 8), then 2x16 HFMA2 per step.
// ---------------------------------------------------------------------------
__global__ void __launch_bounds__(256, 3) k_passA(const float* __restrict__ vin,
                                                  float* __restrict__ vout) {
    __shared__ uint32_t sw[4096];   // 8192 weights as pair-shuffled half2
    const int t = threadIdx.x;
#pragma unroll
    for (int k = 0; k < 8; k++) {
        const int g = t + (k << 8);             // 0..2047 (float4 index)
        const float4 c4 = *(const float4*)(vin + (g << 2));
        sw[2 * g]     = packh2(__fdividef(CSTAR, c4.x), __fdividef(CSTAR, c4.z));
        sw[2 * g + 1] = packh2(__fdividef(CSTAR, c4.y), __fdividef(CSTAR, c4.w));
    }
    __syncthreads();

    const int w = t >> 5, lane = t & 31;
    const int rowa = (blockIdx.x << 4) + (w << 1);
    const uint4* __restrict__ pa =
        ((const uint4*)g_K8) + (size_t)rowa * (NN / 16) + lane;
    const uint4* __restrict__ pb = pa + (NN / 16);
    const uint4* __restrict__ swv = ((const uint4*)sw) + (lane << 1);

    const __half2 z = __floats2half2_rn(0.f, 0.f);
    __half2 aE0 = z, aO0 = z, aE1 = z, aO1 = z;
    __half2 bE0 = z, bO0 = z, bE1 = z, bO1 = z;

#pragma unroll 2
    for (int s = 0; s < 16; s += 4) {
        uint4 qa[4], qb[4];
#pragma unroll
        for (int j = 0; j < 4; j++) {
            qa[j] = pa[(s + j) * 32];
            qb[j] = pb[(s + j) * 32];
        }
#pragma unroll
        for (int j = 0; j < 4; j++) {
            const uint4 w0 = swv[(s + j) << 6];
            const uint4 w1 = swv[((s + j) << 6) + 1];
            aE0 = __hfma2(dE(qa[j].x), u2h(w0.x), aE0);
            aO0 = __hfma2(dO(qa[j].x), u2h(w0.y), aO0);
            aE1 = __hfma2(dE(qa[j].y), u2h(w0.z), aE1);
            aO1 = __hfma2(dO(qa[j].y), u2h(w0.w), aO1);
            aE0 = __hfma2(dE(qa[j].z), u2h(w1.x), aE0);
            aO0 = __hfma2(dO(qa[j].z), u2h(w1.y), aO0);
            aE1 = __hfma2(dE(qa[j].w), u2h(w1.z), aE1);
            aO1 = __hfma2(dO(qa[j].w), u2h(w1.w), aO1);
            bE0 = __hfma2(dE(qb[j].x), u2h(w0.x), bE0);
            bO0 = __hfma2(dO(qb[j].x), u2h(w0.y), bO0);
            bE1 = __hfma2(dE(qb[j].y), u2h(w0.z), bE1);
            bO1 = __hfma2(dO(qb[j].y), u2h(w0.w), bO1);
            bE0 = __hfma2(dE(qb[j].z), u2h(w1.x), bE0);
            bO0 = __hfma2(dO(qb[j].z), u2h(w1.y), bO0);
            bE1 = __hfma2(dE(qb[j].w), u2h(w1.z), bE1);
            bO1 = __hfma2(dO(qb[j].w), u2h(w1.w), bO1);
        }
    }

    __half2 sa = __hadd2(__hadd2(aE0, aO0), __hadd2(aE1, aO1));
    __half2 sb = __hadd2(__hadd2(bE0, bO0), __hadd2(bE1, bO1));
    float va = __low2float(sa) + __high2float(sa);
    float vb = __low2float(sb) + __high2float(sb);
#pragma unroll
    for (int o = 16; o; o >>= 1) {
        va += __shfl_xor_sync(0xFFFFFFFFu, va, o);
        vb += __shfl_xor_sync(0xFFFFFFFFu, vb, o);
    }
    if (lane == 0) {
        vout[rowa]     = va;
        vout[rowa + 1] = vb;
    }
}

// ---------------------------------------------------------------------------
// passB: c[j] += sum_{i in 64-row group} Kd[i,j] * (CSTAR / r[i])
// grid (4, 128): block = 64 rows x 2048 cols, thread = 8 cols (uint2/row).
// Explicit 16-deep uint2 batches (MLP = 16); fp16 chains flushed at 32 rows;
// 8 atomics per thread into the zeroed c slice (128 contributors/address).
// ---------------------------------------------------------------------------
__global__ void __launch_bounds__(256, 3) k_passB(const float* __restrict__ vin,
                                                  float* __restrict__ vout) {
    __shared__ uint32_t swr[64];
    const int t  = threadIdx.x;
    const int r0 = blockIdx.y << 6;
    const int c0 = (blockIdx.x << 11) + (t << 3);
    if (t < 64) {
        const float wv = __fdividef(CSTAR, vin[r0 + t]);
        swr[t] = packh2(wv, wv);
    }
    __syncthreads();

    const uint2* __restrict__ base =
        ((const uint2*)g_K8) + (size_t)r0 * (NN / 8) + (c0 >> 3);

    const __half2 z = __floats2half2_rn(0.f, 0.f);
    __half2 hE0 = z, hO0 = z, hE1 = z, hO1 = z;
    float f0 = 0.f, f1 = 0.f, f2 = 0.f, f3 = 0.f;
    float f4 = 0.f, f5 = 0.f, f6 = 0.f, f7 = 0.f;

#pragma unroll
    for (int b = 0; b < 4; b++) {
        uint2 q[16];
#pragma unroll
        for (int k = 0; k < 16; k++)
            q[k] = base[(size_t)((b << 4) + k) * (NN / 8)];
#pragma unroll
        for (int k = 0; k < 16; k++) {
            const __half2 wr = u2h(swr[(b << 4) + k]);
            hE0 = __hfma2(dE(q[k].x), wr, hE0);
            hO0 = __hfma2(dO(q[k].x), wr, hO0);
            hE1 = __hfma2(dE(q[k].y), wr, hE1);
            hO1 = __hfma2(dO(q[k].y), wr, hO1);
        }
        if (b & 1) {   // flush every 32 rows (chain length cap = 32)
            f0 += __low2float(hE0);  f2 += __high2float(hE0);
            f1 += __low2float(hO0);  f3 += __high2float(hO0);
            f4 += __low2float(hE1);  f6 += __high2float(hE1);
            f5 += __low2float(hO1);  f7 += __high2float(hO1);
            hE0 = z; hO0 = z; hE1 = z; hO1 = z;
        }
    }

    float* vo = vout + c0;
    atomicAdd(vo + 0, f0); atomicAdd(vo + 1, f1);
    atomicAdd(vo + 2, f2); atomicAdd(vo + 3, f3);
    atomicAdd(vo + 4, f4); atomicAdd(vo + 5, f5);
    atomicAdd(vo + 6, f6); atomicAdd(vo + 7, f7);
}

// ---------------------------------------------------------------------------
// loss = -10*S1 + 35*ln2*S3 + <trow, ln r50> + <tcol, ln c50>
// ---------------------------------------------------------------------------
__global__ void __launch_bounds__(1024) k_final(float* __restrict__ out) {
    const int t = threadIdx.x;
    const float* rfin = g_r + (size_t)NITER * NN;
    const float* cfin = g_c + (size_t)NITER * NN;
    float s1 = 0.f, s2 = 0.f, s3 = 0.f;
    for (int i = t; i < NN; i += 1024) {
        const float tr = g_trow[i];
        s1 += tr * logf(rfin[i]);
        s3 += tr;
        s2 += g_tcol[i] * logf(cfin[i]);
    }
    __shared__ float sa[1024], sb[1024], sc[1024];
    sa[t] = s1; sb[t] = s2; sc[t] = s3;
    __syncthreads();
    for (int s = 512; s > 0; s >>= 1) {
        if (t < s) { sa[t] += sa[t + s]; sb[t] += sb[t + s]; sc[t] += sc[t + s]; }
        __syncthreads();
    }
    if (t == 0)
        out[0] = -10.0f * g_S1[0] + 24.260151319598086f * sc[0] + sa[0] + sb[0];
}

// ---------------------------------------------------------------------------
extern "C" void kernel_launch(void* const* d_in, const int* in_sizes, int n_in,
                              void* d_out, int out_size) {
    (void)in_sizes; (void)n_in; (void)out_size;
    const float* M   = (const float*)d_in[0];
    const float* tgt = (const float*)d_in[1];
    float* out = (float*)d_out;

    void *pR, *pC;
    cudaGetSymbolAddress(&pR, g_r);
    cudaGetSymbolAddress(&pC, g_c);
    float* R = (float*)pR;
    float* C = (float*)pC;

    k_init<<<1632, 256>>>();
    k_bt<<<dim3(8, 64), 256>>>(M, tgt);

    for (int k = 1; k <= NITER; k++) {
        k_passA<<<512, 256>>>(C + (size_t)(k - 1) * NN, R + (size_t)k * NN);
        k_passB<<<dim3(4, 128), 256>>>(R + (size_t)k * NN,
                                       C + (size_t)k * NN);
    }
    k_final<<<1, 1024>>>(out);
}